// round 5
// baseline (speedup 1.0000x reference)
#include <cuda_runtime.h>
#include <cuda_fp16.h>

// RoIAlign (torchvision aligned=True, sampling_ratio=2) — two-pass:
//  1) transpose x [B,C,H,W] f32 -> g_xt [B,H,W,C] f16 (channels contiguous)
//  2) gather: block = (bn, channel-quarter). 8 warps; warp per output-position
//     group, lanes span channels -> coalesced loads; smem-staged transpose
//     for coalesced f32 output stores. Grid 2048 @ <=32 regs for 100% occ.

#define B_    8
#define N_    64
#define C_    256
#define H_    128
#define W_    128
#define HW_   (H_ * W_)
#define OUT_H 6
#define OUT_W 6
#define NPOS  36
#define CH_   64             // channels per gather block
#define CH2_  (CH_ / 2)      // 32 half2 per block row

// 8 * 16384 * 256 halves = 64 MB scratch (__device__ global: allowed)
__device__ __half g_xt[(size_t)B_ * HW_ * C_];

// ---------------------------------------------------------------------------
// Pass 1: transpose [C, HW] f32 tile -> [HW, C] f16. DRAM-bound (~6.2 TB/s).
// ---------------------------------------------------------------------------
__global__ void __launch_bounds__(256)
transpose_kernel(const float* __restrict__ x)
{
    __shared__ float sm[64][33];

    const int b  = blockIdx.z;
    const int c0 = blockIdx.y * 64;
    const int s0 = blockIdx.x * 32;
    const int tid = threadIdx.x;
    const int tx = tid & 31;
    const int ty = tid >> 5;

    const float* src = x + ((size_t)b * C_ + c0) * HW_ + s0;
    #pragma unroll
    for (int r = 0; r < 8; r++) {
        int cl = ty + 8 * r;
        sm[cl][tx] = src[(size_t)cl * HW_ + tx];
    }
    __syncthreads();

    __half2* dst = (__half2*)g_xt;
    const size_t dbase = ((size_t)b * HW_ + s0) * (C_ / 2) + (c0 >> 1) + tx;
    #pragma unroll
    for (int r = 0; r < 4; r++) {
        int sl = ty + 8 * r;
        float v0 = sm[2 * tx + 0][sl];
        float v1 = sm[2 * tx + 1][sl];
        dst[dbase + (size_t)sl * (C_ / 2)] = __floats2half2_rn(v0, v1);
    }
}

// ---------------------------------------------------------------------------
// Pass 2: gather. blockIdx.x = bn*4 + cq. 8 warps; warp w handles positions
// w, w+8, ... Lane l covers the half2 channel pair (cq*64 + 2l) -> every
// corner fetch is one coalesced 128B transaction per warp.
// ---------------------------------------------------------------------------
__global__ void __launch_bounds__(256, 8)
gather_kernel(const float* __restrict__ boxes, float* __restrict__ out)
{
    __shared__ float tile[NPOS][CH_ + 2];   // row stride 66 floats (8B-aligned)

    const int blk  = blockIdx.x;
    const int bn   = blk >> 2;            // b*64 + n
    const int cq   = blk & 3;             // channel quarter
    const int b    = bn >> 6;
    const int tid  = threadIdx.x;
    const int lane = tid & 31;
    const int w    = tid >> 5;

    const float* box = boxes + bn * 4;
    const float x1 = __ldg(box + 0) - 0.5f;
    const float y1 = __ldg(box + 1) - 0.5f;
    const float x2 = __ldg(box + 2) - 0.5f;
    const float y2 = __ldg(box + 3) - 0.5f;
    const float bw = (x2 - x1) * (1.0f / OUT_W);
    const float bh = (y2 - y1) * (1.0f / OUT_H);

    const __half2* xt = (const __half2*)g_xt
                      + (size_t)b * HW_ * (C_ / 2) + cq * CH2_ + lane;

    for (int pos = w; pos < NPOS; pos += 8) {
        const int oh = pos / 6;
        const int ow = pos - 6 * oh;

        int   yl[2], yh[2], xl[2], xh[2];
        float wy0[2], wy1[2], wx0[2], wx1[2];
        #pragma unroll
        for (int i = 0; i < 2; i++) {
            float yy = y1 + ((float)oh + ((float)i + 0.5f) * 0.5f) * bh;
            bool  vy = (yy >= -1.0f) && (yy <= (float)H_);
            float cy = fmaxf(yy, 0.0f);
            int   lo = (int)floorf(cy);
            bool  ey = (lo >= H_ - 1);
            yl[i] = ey ? (H_ - 1) : lo;
            yh[i] = ey ? (H_ - 1) : (lo + 1);
            float fy = ey ? 0.0f : (cy - (float)lo);
            wy1[i] = vy ? fy : 0.0f;
            wy0[i] = vy ? (1.0f - fy) : 0.0f;

            float xx = x1 + ((float)ow + ((float)i + 0.5f) * 0.5f) * bw;
            bool  vx = (xx >= -1.0f) && (xx <= (float)W_);
            float cx = fmaxf(xx, 0.0f);
            int   lx = (int)floorf(cx);
            bool  ex = (lx >= W_ - 1);
            xl[i] = ex ? (W_ - 1) : lx;
            xh[i] = ex ? (W_ - 1) : (lx + 1);
            float fx = ex ? 0.0f : (cx - (float)lx);
            wx1[i] = vx ? fx : 0.0f;
            wx0[i] = vx ? (1.0f - fx) : 0.0f;
        }

        float2 acc = make_float2(0.0f, 0.0f);

        #pragma unroll
        for (int iy = 0; iy < 2; iy++) {
            #pragma unroll
            for (int ix = 0; ix < 2; ix++) {
                const int   cyi[4] = { yl[iy], yl[iy], yh[iy], yh[iy] };
                const int   cxi[4] = { xl[ix], xh[ix], xl[ix], xh[ix] };
                const float cwt[4] = { wy0[iy] * wx0[ix], wy0[iy] * wx1[ix],
                                       wy1[iy] * wx0[ix], wy1[iy] * wx1[ix] };
                #pragma unroll
                for (int c4 = 0; c4 < 4; c4++) {
                    float2 f = __half22float2(
                        xt[(size_t)(cyi[c4] * W_ + cxi[c4]) * (C_ / 2)]);
                    acc.x += cwt[c4] * f.x;
                    acc.y += cwt[c4] * f.y;
                }
            }
        }

        float2* row = (float2*)&tile[pos][0];
        row[lane] = make_float2(acc.x * 0.25f, acc.y * 0.25f);
    }
    __syncthreads();

    // Block's output slab: 64 channels x 36 pos = 2304 contiguous floats.
    float* obase = out + (size_t)bn * (C_ * NPOS) + (size_t)cq * CH_ * NPOS;
    #pragma unroll
    for (int i = 0; i < 9; i++) {
        int e   = i * 256 + tid;
        int c   = e / 36;
        int pos = e - 36 * c;
        obase[e] = tile[pos][c];
    }
}

extern "C" void kernel_launch(void* const* d_in, const int* in_sizes, int n_in,
                              void* d_out, int out_size)
{
    const float* x     = (const float*)d_in[0];
    const float* boxes = (const float*)d_in[1];
    float*       out   = (float*)d_out;

    dim3 tgrid(HW_ / 32, C_ / 64, B_);      // 512 x 4 x 8
    transpose_kernel<<<tgrid, 256>>>(x);
    gather_kernel<<<B_ * N_ * 4, 256>>>(boxes, out);
}

// round 6
// speedup vs baseline: 1.2295x; 1.2295x over previous
#include <cuda_runtime.h>
#include <cuda_fp16.h>

// RoIAlign (torchvision aligned=True, sampling_ratio=2) — two-pass:
//  1) transpose x [B,C,H,W] f32 -> g_xt [B,H,W,C] f16 (channels contiguous)
//  2) gather: warp covers ALL 256 channels per corner via one LDG.128/lane
//     (uint4 = 8 fp16 channels). Setup amortized over 256 channels.
//     Grid 1024 = (bn, oh-half); 6 warps/block, 3 positions/warp.

#define B_    8
#define N_    64
#define C_    256
#define C2_   (C_ / 2)       // 128 half2
#define H_    128
#define W_    128
#define HW_   (H_ * W_)
#define OUT_H 6
#define OUT_W 6
#define NPOS  36
#define PPB   18             // positions per block (3 oh rows)
#define WPB   6              // warps per block
#define TPB   (WPB * 32)     // 192 threads

// 8 * 16384 * 256 halves = 64 MB scratch (__device__ global: allowed)
__device__ __half g_xt[(size_t)B_ * HW_ * C_];

// ---------------------------------------------------------------------------
// Pass 1: transpose [C, HW] f32 tile -> [HW, C] f16. DRAM-bound (~6.2 TB/s).
// ---------------------------------------------------------------------------
__global__ void __launch_bounds__(256)
transpose_kernel(const float* __restrict__ x)
{
    __shared__ float sm[64][33];

    const int b  = blockIdx.z;
    const int c0 = blockIdx.y * 64;
    const int s0 = blockIdx.x * 32;
    const int tid = threadIdx.x;
    const int tx = tid & 31;
    const int ty = tid >> 5;

    const float* src = x + ((size_t)b * C_ + c0) * HW_ + s0;
    #pragma unroll
    for (int r = 0; r < 8; r++) {
        int cl = ty + 8 * r;
        sm[cl][tx] = src[(size_t)cl * HW_ + tx];
    }
    __syncthreads();

    __half2* dst = (__half2*)g_xt;
    const size_t dbase = ((size_t)b * HW_ + s0) * C2_ + (c0 >> 1) + tx;
    #pragma unroll
    for (int r = 0; r < 4; r++) {
        int sl = ty + 8 * r;
        float v0 = sm[2 * tx + 0][sl];
        float v1 = sm[2 * tx + 1][sl];
        dst[dbase + (size_t)sl * C2_] = __floats2half2_rn(v0, v1);
    }
}

// ---------------------------------------------------------------------------
// Pass 2: gather. blockIdx.x = bn*2 + half. Warp w handles local positions
// w, w+6, w+12 within this half's 18 positions. Lane l accumulates channels
// 8l..8l+7 (one uint4 = 4 half2 per corner load, fully coalesced 512B/warp).
// ---------------------------------------------------------------------------
__global__ void __launch_bounds__(TPB)
gather_kernel(const float* __restrict__ boxes, float* __restrict__ out)
{
    __shared__ float tile[PPB][C_ + 2];   // row stride 258 floats (8B-aligned rows)

    const int blk  = blockIdx.x;
    const int bn   = blk >> 1;            // b*64 + n
    const int half = blk & 1;             // oh rows 0-2 or 3-5
    const int b    = bn >> 6;
    const int tid  = threadIdx.x;
    const int lane = tid & 31;
    const int w    = tid >> 5;

    const float* box = boxes + bn * 4;
    const float bx1 = __ldg(box + 0) - 0.5f;
    const float by1 = __ldg(box + 1) - 0.5f;
    const float bx2 = __ldg(box + 2) - 0.5f;
    const float by2 = __ldg(box + 3) - 0.5f;
    const float bw = (bx2 - bx1) * (1.0f / OUT_W);
    const float bh = (by2 - by1) * (1.0f / OUT_H);

    // batch base as uint4*: pixel p occupies 32 uint4 (256 ch * 2B / 16B)
    const uint4* xt4 = (const uint4*)g_xt + (size_t)b * HW_ * 32 + lane;

    #pragma unroll
    for (int pl = 0; pl < 3; pl++) {
        const int pos = w + 6 * pl;                 // 0..17 local
        const int gpos = half * PPB + pos;          // 0..35 global
        const int oh = gpos / 6;
        const int ow = gpos - 6 * oh;

        int   yl[2], yh[2], xl[2], xh[2];
        float wy0[2], wy1[2], wx0[2], wx1[2];
        #pragma unroll
        for (int i = 0; i < 2; i++) {
            float yy = by1 + ((float)oh + ((float)i + 0.5f) * 0.5f) * bh;
            bool  vy = (yy >= -1.0f) && (yy <= (float)H_);
            float cy = fmaxf(yy, 0.0f);
            int   lo = (int)floorf(cy);
            bool  ey = (lo >= H_ - 1);
            yl[i] = ey ? (H_ - 1) : lo;
            yh[i] = ey ? (H_ - 1) : (lo + 1);
            float fy = ey ? 0.0f : (cy - (float)lo);
            wy1[i] = vy ? fy : 0.0f;
            wy0[i] = vy ? (1.0f - fy) : 0.0f;

            float xx = bx1 + ((float)ow + ((float)i + 0.5f) * 0.5f) * bw;
            bool  vx = (xx >= -1.0f) && (xx <= (float)W_);
            float cx = fmaxf(xx, 0.0f);
            int   lx = (int)floorf(cx);
            bool  ex = (lx >= W_ - 1);
            xl[i] = ex ? (W_ - 1) : lx;
            xh[i] = ex ? (W_ - 1) : (lx + 1);
            float fx = ex ? 0.0f : (cx - (float)lx);
            wx1[i] = vx ? fx : 0.0f;
            wx0[i] = vx ? (1.0f - fx) : 0.0f;
        }

        float acc[8];
        #pragma unroll
        for (int k = 0; k < 8; k++) acc[k] = 0.0f;

        #pragma unroll
        for (int iy = 0; iy < 2; iy++) {
            #pragma unroll
            for (int ix = 0; ix < 2; ix++) {
                // 2x2 pixel corners of this sample point
                const int p00 = (yl[iy] * W_ + xl[ix]) * 32;
                const int p01 = (yl[iy] * W_ + xh[ix]) * 32;
                const int p10 = (yh[iy] * W_ + xl[ix]) * 32;
                const int p11 = (yh[iy] * W_ + xh[ix]) * 32;
                const float w00 = wy0[iy] * wx0[ix];
                const float w01 = wy0[iy] * wx1[ix];
                const float w10 = wy1[iy] * wx0[ix];
                const float w11 = wy1[iy] * wx1[ix];

                uint4 v00 = __ldg(xt4 + p00);
                uint4 v01 = __ldg(xt4 + p01);
                uint4 v10 = __ldg(xt4 + p10);
                uint4 v11 = __ldg(xt4 + p11);

                const uint4* vs[4] = { &v00, &v01, &v10, &v11 };
                const float  ws[4] = { w00, w01, w10, w11 };
                #pragma unroll
                for (int c4 = 0; c4 < 4; c4++) {
                    const __half2* h = (const __half2*)vs[c4];
                    const float wgt = ws[c4];
                    #pragma unroll
                    for (int j = 0; j < 4; j++) {
                        float2 f = __half22float2(h[j]);
                        acc[2 * j + 0] += wgt * f.x;
                        acc[2 * j + 1] += wgt * f.y;
                    }
                }
            }
        }

        // lane's channels: 8*lane .. 8*lane+7
        float2* row = (float2*)&tile[pos][0];     // 8B-aligned (stride 258)
        #pragma unroll
        for (int j = 0; j < 4; j++) {
            row[4 * lane + j] = make_float2(acc[2 * j] * 0.25f,
                                            acc[2 * j + 1] * 0.25f);
        }
    }
    __syncthreads();

    // Output slab: for each c, 18 contiguous floats at c*36 + half*18.
    float* obase = out + (size_t)bn * (C_ * NPOS) + half * PPB;
    #pragma unroll
    for (int i = 0; i < (C_ * PPB) / TPB; i++) {   // 24 iterations
        int e = i * TPB + tid;
        int c = e / PPB;
        int p = e - PPB * c;
        obase[c * NPOS + p] = tile[p][c];
    }
}

extern "C" void kernel_launch(void* const* d_in, const int* in_sizes, int n_in,
                              void* d_out, int out_size)
{
    const float* x     = (const float*)d_in[0];
    const float* boxes = (const float*)d_in[1];
    float*       out   = (float*)d_out;

    dim3 tgrid(HW_ / 32, C_ / 64, B_);      // 512 x 4 x 8
    transpose_kernel<<<tgrid, 256>>>(x);
    gather_kernel<<<B_ * N_ * 2, TPB>>>(boxes, out);
}